// round 13
// baseline (speedup 1.0000x reference)
#include <cuda_runtime.h>
#include <cstdint>

// VDPDropout fused single-kernel (RPB=1, terminal granularity):
//   mu_out    = keep ? mu*1.25 : 0                       [B, H]
//   Sigma_out = 1.5625 * Sigma * (nz_i & nz_j)           [B, H, H]
// One block per Sigma row. Vectorized setup (1x float4 mu + 1x vec4 mask per
// thread, kind hoisted). Column flags in registers; ONE row-predicate byte
// crosses threads. Dropped row skipped via a PREDICATED load (@P LDG).

#define B 32
#define H 2048
#define BH (B * H)              // 65536
#define GRID BH                 // one block per row

// Predicated streaming vec4 load: returns {0,0,0,0} when pred==0, no traffic.
__device__ __forceinline__ float4 ldcs_pred(const float4* p, int pred) {
    float4 v = make_float4(0.f, 0.f, 0.f, 0.f);
    asm volatile(
        "{\n\t.reg .pred p;\n\t"
        "setp.ne.s32 p, %4, 0;\n\t"
        "@p ld.global.cs.v4.f32 {%0,%1,%2,%3}, [%5];\n\t}"
        : "+f"(v.x), "+f"(v.y), "+f"(v.z), "+f"(v.w)
        : "r"(pred), "l"(p));
    return v;
}

__global__ void __launch_bounds__(512)
fused_kernel(const float* __restrict__ mu,
             const unsigned int* __restrict__ mask,
             float* __restrict__ mu_out,
             const float4* __restrict__ Sin,
             float4* __restrict__ Sout) {
    int r0    = blockIdx.x;             // the row this block owns
    int b     = r0 >> 11;               // batch index
    int rbase = r0 & (H - 1);           // row offset within batch
    __shared__ unsigned char s_rowpred; // nz flag for row rbase

    // ---- mask dtype detection: ONE combined reduction ----
    unsigned int w = (threadIdx.x < 256) ? mask[threadIdx.x] : 0u;
    int bad = 0;
    if (threadIdx.x < 256) {
        bad  = (w > 1u) ? 1 : 0;                                  // not int32 {0,1}
        bad |= ((w != 0u) && (w != 0x3F800000u)) ? 2 : 0;         // not f32 {0,1.0}
    }
    int anybad = __syncthreads_or(bad);
    int kind = !(anybad & 1) ? 0 : (!(anybad & 2) ? 1 : 2);

    // ---- per-thread: own 4 columns, VECTORIZED (2 LDGs total) ----
    int t = threadIdx.x;                // 0..511, 4 elems each = 2048
    int v4i = b * (H / 4) + t;          // float4/int4 index of this thread's quad

    float4 muv = reinterpret_cast<const float4*>(mu)[v4i];

    bool k0, k1, k2, k3;
    if (kind == 0) {
        int4 m = reinterpret_cast<const int4*>(mask)[v4i];
        k0 = m.x != 0; k1 = m.y != 0; k2 = m.z != 0; k3 = m.w != 0;
    } else if (kind == 1) {
        float4 m = reinterpret_cast<const float4*>(mask)[v4i];
        k0 = m.x != 0.0f; k1 = m.y != 0.0f; k2 = m.z != 0.0f; k3 = m.w != 0.0f;
    } else {
        uchar4 m = reinterpret_cast<const uchar4*>(mask)[v4i];
        k0 = m.x != 0; k1 = m.y != 0; k2 = m.z != 0; k3 = m.w != 0;
    }

    float4 mo;
    mo.x = k0 ? muv.x * 1.25f : 0.0f;
    mo.y = k1 ? muv.y * 1.25f : 0.0f;
    mo.z = k2 ? muv.z * 1.25f : 0.0f;
    mo.w = k3 ? muv.w * 1.25f : 0.0f;

    unsigned char n0 = mo.x != 0.0f, n1 = mo.y != 0.0f;
    unsigned char n2 = mo.z != 0.0f, n3 = mo.w != 0.0f;

    // the thread owning column rbase publishes the row predicate (1 byte)
    if (t == (rbase >> 2)) {
        int q = rbase & 3;
        s_rowpred = (q == 0) ? n0 : (q == 1) ? n1 : (q == 2) ? n2 : n3;
    }

    // one block per batch (row 0 of the batch) also writes mu_out
    if (rbase == 0)
        reinterpret_cast<float4*>(mu_out)[v4i] = mo;
    __syncthreads();

    bool c0 = n0, c1 = n1, c2 = n2, c3 = n3;     // column flags (registers)
    int p0 = s_rowpred;

    const float4* src = Sin + (size_t)r0 * (H / 4) + t;
    float4*       dst = Sout + (size_t)r0 * (H / 4) + t;

    // ---- Sigma stream: one predicated load + one store ----
    float4 v0 = ldcs_pred(src, p0);

    // v == 0 for a dropped row, so column predicates suffice.
    float4 w0;
    w0.x = c0 ? v0.x * 1.5625f : 0.f;
    w0.y = c1 ? v0.y * 1.5625f : 0.f;
    w0.z = c2 ? v0.z * 1.5625f : 0.f;
    w0.w = c3 ? v0.w * 1.5625f : 0.f;

    __stcs(dst, w0);
}

// ---------------------------------------------------------------------------
extern "C" void kernel_launch(void* const* d_in, const int* in_sizes, int n_in,
                              void* d_out, int out_size) {
    const float* mu_in    = (const float*)d_in[0];
    const void*  sigma_in = d_in[1];
    const void*  mask     = d_in[2];

    float* mu_out    = (float*)d_out;
    float* sigma_out = (float*)d_out + BH;

    fused_kernel<<<GRID, 512>>>(mu_in, (const unsigned int*)mask, mu_out,
                                (const float4*)sigma_in, (float4*)sigma_out);
}

// round 14
// speedup vs baseline: 1.2232x; 1.2232x over previous
#include <cuda_runtime.h>
#include <cstdint>

// VDPDropout fused single-kernel (FINAL = R12 optimum: RPB=2):
//   mu_out    = keep ? mu*1.25 : 0                       [B, H]
//   Sigma_out = 1.5625 * Sigma * (nz_i & nz_j)           [B, H, H]
// Vectorized setup (1x float4 mu + 1x vec4 mask per thread, kind hoisted).
// Column flags in registers; 2 row-predicate bytes cross threads. Dropped rows
// skipped via PREDICATED loads (@P LDG); straight-line 2-load stream body.
// RPB sweep: 32->150.3, 16->147.5, 8->147.1, 4->143.9, 2->142.6, 1->173.4us.

#define B 32
#define H 2048
#define BH (B * H)              // 65536
#define RPB 2                   // rows per block; 2 | 2048 -> no batch straddle
#define GRID (BH / RPB)         // 32768

// Predicated streaming vec4 load: returns {0,0,0,0} when pred==0, no traffic.
__device__ __forceinline__ float4 ldcs_pred(const float4* p, int pred) {
    float4 v = make_float4(0.f, 0.f, 0.f, 0.f);
    asm volatile(
        "{\n\t.reg .pred p;\n\t"
        "setp.ne.s32 p, %4, 0;\n\t"
        "@p ld.global.cs.v4.f32 {%0,%1,%2,%3}, [%5];\n\t}"
        : "+f"(v.x), "+f"(v.y), "+f"(v.z), "+f"(v.w)
        : "r"(pred), "l"(p));
    return v;
}

__global__ void __launch_bounds__(512)
fused_kernel(const float* __restrict__ mu,
             const unsigned int* __restrict__ mask,
             float* __restrict__ mu_out,
             const float4* __restrict__ Sin,
             float4* __restrict__ Sout) {
    int r0    = blockIdx.x * RPB;       // first row this block owns
    int b     = r0 >> 11;               // batch index
    int rbase = r0 & (H - 1);           // row offset within batch (2-aligned)
    __shared__ uchar2 s_rowpred;        // nz flags for rows rbase, rbase+1

    // ---- mask dtype detection: ONE combined reduction ----
    unsigned int w = (threadIdx.x < 256) ? mask[threadIdx.x] : 0u;
    int bad = 0;
    if (threadIdx.x < 256) {
        bad  = (w > 1u) ? 1 : 0;                                  // not int32 {0,1}
        bad |= ((w != 0u) && (w != 0x3F800000u)) ? 2 : 0;         // not f32 {0,1.0}
    }
    int anybad = __syncthreads_or(bad);
    int kind = !(anybad & 1) ? 0 : (!(anybad & 2) ? 1 : 2);

    // ---- per-thread: own 4 columns, VECTORIZED (2 LDGs total) ----
    int t = threadIdx.x;                // 0..511, 4 elems each = 2048
    int v4i = b * (H / 4) + t;          // float4/int4 index of this thread's quad

    float4 muv = reinterpret_cast<const float4*>(mu)[v4i];

    bool k0, k1, k2, k3;
    if (kind == 0) {
        int4 m = reinterpret_cast<const int4*>(mask)[v4i];
        k0 = m.x != 0; k1 = m.y != 0; k2 = m.z != 0; k3 = m.w != 0;
    } else if (kind == 1) {
        float4 m = reinterpret_cast<const float4*>(mask)[v4i];
        k0 = m.x != 0.0f; k1 = m.y != 0.0f; k2 = m.z != 0.0f; k3 = m.w != 0.0f;
    } else {
        uchar4 m = reinterpret_cast<const uchar4*>(mask)[v4i];
        k0 = m.x != 0; k1 = m.y != 0; k2 = m.z != 0; k3 = m.w != 0;
    }

    float4 mo;
    mo.x = k0 ? muv.x * 1.25f : 0.0f;
    mo.y = k1 ? muv.y * 1.25f : 0.0f;
    mo.z = k2 ? muv.z * 1.25f : 0.0f;
    mo.w = k3 ? muv.w * 1.25f : 0.0f;

    unsigned char n0 = mo.x != 0.0f, n1 = mo.y != 0.0f;
    unsigned char n2 = mo.z != 0.0f, n3 = mo.w != 0.0f;

    // the thread owning columns (rbase, rbase+1) publishes the row predicates.
    // rbase is 2-aligned: the pair lives in one thread's quad, halves selected
    // by bit 1 of rbase.
    if (t == (rbase >> 2))
        s_rowpred = (rbase & 2) ? make_uchar2(n2, n3) : make_uchar2(n0, n1);

    // one block per batch (rows [0,RPB)) also writes mu_out
    if (rbase == 0)
        reinterpret_cast<float4*>(mu_out)[v4i] = mo;
    __syncthreads();

    bool c0 = n0, c1 = n1, c2 = n2, c3 = n3;     // column flags (registers)
    uchar2 rp = s_rowpred;
    int p0 = rp.x, p1 = rp.y;

    const float4* src = Sin + (size_t)r0 * (H / 4) + t;
    float4*       dst = Sout + (size_t)r0 * (H / 4) + t;
    const size_t o1 = (size_t)(H / 4);

    // ---- Sigma stream: straight-line pair of rows (MLP=2) ----
    float4 v0 = ldcs_pred(src,      p0);
    float4 v1 = ldcs_pred(src + o1, p1);

    // v == 0 for dropped rows, so column predicates suffice.
    float4 w0, w1;
    w0.x = c0 ? v0.x * 1.5625f : 0.f; w0.y = c1 ? v0.y * 1.5625f : 0.f;
    w0.z = c2 ? v0.z * 1.5625f : 0.f; w0.w = c3 ? v0.w * 1.5625f : 0.f;
    w1.x = c0 ? v1.x * 1.5625f : 0.f; w1.y = c1 ? v1.y * 1.5625f : 0.f;
    w1.z = c2 ? v1.z * 1.5625f : 0.f; w1.w = c3 ? v1.w * 1.5625f : 0.f;

    __stcs(dst,      w0);
    __stcs(dst + o1, w1);
}

// ---------------------------------------------------------------------------
extern "C" void kernel_launch(void* const* d_in, const int* in_sizes, int n_in,
                              void* d_out, int out_size) {
    const float* mu_in    = (const float*)d_in[0];
    const void*  sigma_in = d_in[1];
    const void*  mask     = d_in[2];

    float* mu_out    = (float*)d_out;
    float* sigma_out = (float*)d_out + BH;

    fused_kernel<<<GRID, 512>>>(mu_in, (const unsigned int*)mask, mu_out,
                                (const float4*)sigma_in, (float4*)sigma_out);
}